// round 17
// baseline (speedup 1.0000x reference)
#include <cuda_runtime.h>
#include <math.h>
#include <stdint.h>

// MoE router: logits = x @ W^T  ([16384,2048] x [2048,8]), top-2 + softmax.
// Output layout (fp32): [indices 16384*2][gates 16384*2][logits 16384*8].
//
// R15 structure (W in smem -> global FIFO carries only x; continuous
// cross-group cp.async pipeline; tree-reduction epilogue; scalar FMA), with
// the warp count chosen for BALANCE: 148 blocks x 7 warps = 1036 warps,
// ceil(4096/1036)=4 groups/warp -> 98.8% work balance (R15's 16 warps gave
// 1.73 avg -> 2 makespan = 86.5%, the measured 69% DRAM ceiling).
// Freed smem deepens the pipeline: NSTAGE=8 -> ~14KB/warp, ~98KB/SM in
// flight, far above the latency-hiding bar.

#define DDIM 2048
#define NEXP 8
#define TGRP 4
#define CHUNKS (DDIM / 128)        // 16 chunks of 128 floats (4 per lane)
#define W_FLOATS (NEXP * DDIM)     // 16384
#define NWARP 7
#define THREADS (NWARP * 32)       // 224
#define NSTAGE 8
#define STAGE_FLOATS (TGRP * 128)  // 512 floats = 2KB
#define XBUF_FLOATS (NWARP * NSTAGE * STAGE_FLOATS)   // 28672
#define SMEM_BYTES ((W_FLOATS + XBUF_FLOATS) * 4)     // 64KB + 112KB = 176KB
#define NBLOCK 148

__device__ __forceinline__ void cp_async16(uint32_t dst, const float* src) {
    asm volatile("cp.async.cg.shared.global [%0], [%1], 16;"
                 :: "r"(dst), "l"(src));
}
__device__ __forceinline__ void cp_commit() {
    asm volatile("cp.async.commit_group;");
}
__device__ __forceinline__ void cp_waitN() {
    asm volatile("cp.async.wait_group %0;" :: "n"(NSTAGE - 1));
}

__global__ __launch_bounds__(THREADS, 1)
void router_kernel(const float* __restrict__ x,
                   const float* __restrict__ w,
                   float* __restrict__ out,
                   int n_tokens, int groups_total)
{
    extern __shared__ float smem[];
    float* ws = smem;                       // [NEXP][DDIM]
    const int lane = threadIdx.x & 31;
    const int wid  = threadIdx.x >> 5;

    // Cooperative W load (4096 float4s over 224 threads).
    {
        const float4* wsrc = reinterpret_cast<const float4*>(w);
        float4* wdst = reinterpret_cast<float4*>(ws);
        for (int i = threadIdx.x; i < W_FLOATS / 4; i += THREADS)
            wdst[i] = wsrc[i];
    }
    __syncthreads();

    float* xbuf = smem + W_FLOATS + wid * (NSTAGE * STAGE_FLOATS);
    const uint32_t xbuf_u32 =
        (uint32_t)__cvta_generic_to_shared(xbuf) + lane * 16;

    // Warp-major group assignment: spreads multi-group warps over all SMs.
    const int gw      = wid * NBLOCK + (int)blockIdx.x;
    const int gstride = NBLOCK * NWARP;                 // 1036
    const int ngroups = (gw < groups_total)
                      ? (groups_total - 1 - gw) / gstride + 1 : 0;

    float* out_idx    = out;
    float* out_gate   = out + (size_t)n_tokens * 2;
    float* out_logits = out + (size_t)n_tokens * 4;

    const float* wsl = ws + lane * 4;

    if (ngroups == 0) return;

    // Pipeline prologue: chunks 0..NSTAGE-1 of this warp's stream (first
    // group, crossing into the second for NSTAGE > CHUNKS; here 8 <= 16).
    {
        const float* xp0 = x + (size_t)(gw * TGRP) * DDIM + lane * 4;
        #pragma unroll
        for (int c = 0; c < NSTAGE; c++) {
            #pragma unroll
            for (int t = 0; t < TGRP; t++)
                cp_async16(xbuf_u32 + (c * STAGE_FLOATS + t * 128) * 4,
                           xp0 + (size_t)t * DDIM + c * 128);
            cp_commit();
        }
    }

    for (int k = 0; k < ngroups; k++) {
        const int g    = gw + k * gstride;
        const int tok0 = g * TGRP;
        const float* xp = x + (size_t)tok0 * DDIM + lane * 4;
        const bool has_next = (k + 1 < ngroups);
        const float* xp_n = has_next
            ? x + (size_t)((g + gstride) * TGRP) * DDIM + lane * 4 : xp;

        float acc[TGRP][NEXP];
        #pragma unroll
        for (int t = 0; t < TGRP; t++)
            #pragma unroll
            for (int e = 0; e < NEXP; e++)
                acc[t][e] = 0.0f;

        #pragma unroll
        for (int c = 0; c < CHUNKS; c++) {
            cp_waitN();   // <=NSTAGE-1 groups pending -> chunk c complete
            const float* stage = xbuf + (c & (NSTAGE - 1)) * STAGE_FLOATS;

            float4 xv[TGRP];
            #pragma unroll
            for (int t = 0; t < TGRP; t++)
                xv[t] = *reinterpret_cast<const float4*>(stage + t * 128 + lane * 4);

            #pragma unroll
            for (int e = 0; e < NEXP; e++) {
                float4 wv = *reinterpret_cast<const float4*>(wsl + e * DDIM + c * 128);
                #pragma unroll
                for (int t = 0; t < TGRP; t++) {
                    acc[t][e] = fmaf(xv[t].x, wv.x,
                                fmaf(xv[t].y, wv.y,
                                fmaf(xv[t].z, wv.z,
                                fmaf(xv[t].w, wv.w, acc[t][e]))));
                }
            }

            // Continuous refill: stream chunk c+NSTAGE (next group's rows
            // once past the tail) -> DRAM stays busy through the epilogue.
            const uint32_t sdst =
                xbuf_u32 + ((c & (NSTAGE - 1)) * STAGE_FLOATS) * 4;
            if (c < CHUNKS - NSTAGE) {
                #pragma unroll
                for (int t = 0; t < TGRP; t++)
                    cp_async16(sdst + t * 128 * 4,
                               xp + (size_t)t * DDIM + (c + NSTAGE) * 128);
            } else if (has_next) {
                #pragma unroll
                for (int t = 0; t < TGRP; t++)
                    cp_async16(sdst + t * 128 * 4,
                               xp_n + (size_t)t * DDIM + (c - (CHUNKS - NSTAGE)) * 128);
            }
            cp_commit();
        }

        // ---- Epilogue (next group's loads already in flight) ----
        // 31-shfl tree reduction: lane v ends with
        // logit(token tok0 + (v>>3), expert v&7).
        float val[32];
        #pragma unroll
        for (int t = 0; t < TGRP; t++)
            #pragma unroll
            for (int e = 0; e < NEXP; e++)
                val[t * NEXP + e] = acc[t][e];

        #pragma unroll
        for (int i = 0; i < 5; i++) {
            const int off = 16 >> i;
            const int n   = 16 >> i;
            const bool up = (lane & off) != 0;
            #pragma unroll
            for (int j = 0; j < n; j++) {
                float keep = up ? val[j + n] : val[j];
                float send = up ? val[j]     : val[j + n];
                float recv = __shfl_xor_sync(0xffffffffu, send, off);
                val[j] = keep + recv;
            }
        }
        const float logit = val[0];

        // Coalesced logits store: 32 contiguous floats, one per lane.
        out_logits[(size_t)tok0 * NEXP + lane] = logit;

        // Gather this token's 8 logits (token = lane & 3 for lanes 0..3).
        float le[NEXP];
        const int tsel = lane & 3;
        #pragma unroll
        for (int e = 0; e < NEXP; e++)
            le[e] = __shfl_sync(0xffffffffu, logit, tsel * NEXP + e);

        if (lane < TGRP) {
            const int tok = tok0 + lane;

            // top-2 (ties -> lower index, matching jax.lax.top_k)
            int i0 = 0; float v0 = le[0];
            #pragma unroll
            for (int e = 1; e < NEXP; e++)
                if (le[e] > v0) { v0 = le[e]; i0 = e; }
            int i1 = -1; float v1 = -INFINITY;
            #pragma unroll
            for (int e = 0; e < NEXP; e++)
                if (e != i0 && le[e] > v1) { v1 = le[e]; i1 = e; }

            // softmax over [v0, v1] with v0 = max
            float ex = __expf(v1 - v0);
            float g0 = 1.0f / (1.0f + ex);
            float g1 = ex * g0;

            *reinterpret_cast<float2*>(out_idx  + (size_t)tok * 2) =
                make_float2((float)i0, (float)i1);
            *reinterpret_cast<float2*>(out_gate + (size_t)tok * 2) =
                make_float2(g0, g1);
        }
    }
}

extern "C" void kernel_launch(void* const* d_in, const int* in_sizes, int n_in,
                              void* d_out, int out_size)
{
    const float* x = (const float*)d_in[0];
    const float* w = (const float*)d_in[1];
    float* out = (float*)d_out;

    const int n_tokens = in_sizes[0] / DDIM;     // 16384
    const int groups   = n_tokens / TGRP;        // 4096

    cudaFuncSetAttribute(router_kernel,
                         cudaFuncAttributeMaxDynamicSharedMemorySize,
                         SMEM_BYTES);

    router_kernel<<<NBLOCK, THREADS, SMEM_BYTES>>>(x, w, out, n_tokens, groups);
}